// round 17
// baseline (speedup 1.0000x reference)
#include <cuda_runtime.h>
#include <math.h>

#define TT    1000
#define BB    128
#define NIN   85
#define NRNN  512
#define NOUT  33
#define MM    (TT * BB)     /* 128000 rows */
#define STEP  (BB * NRNN)   /* 65536 */
#define CH    8             /* steps per chunk in fused kernel; divides 1000 */
#define NCH   (TT / CH)     /* 125 chunks */
#define KP    44            /* k-pairs (88 >= 85, padded with zero weights) */

typedef unsigned long long u64;

// ---------------------------------------------------------------------------
// Packed f32x2 helpers (exact IEEE fp32 per lane; 2x FFMA rate on sm_103a)
// ---------------------------------------------------------------------------
__device__ __forceinline__ u64 pack2(float lo, float hi) {
    u64 r; asm("mov.b64 %0, {%1, %2};" : "=l"(r) : "f"(lo), "f"(hi)); return r;
}
__device__ __forceinline__ void unpack2(u64 v, float& lo, float& hi) {
    asm("mov.b64 {%0, %1}, %2;" : "=f"(lo), "=f"(hi) : "l"(v));
}
__device__ __forceinline__ u64 fma2(u64 a, u64 b, u64 c) {
    u64 d; asm("fma.rn.f32x2 %0, %1, %2, %3;" : "=l"(d) : "l"(a), "l"(b), "l"(c));
    return d;
}
__device__ __forceinline__ unsigned s2u(const void* p) {
    return (unsigned)__cvta_generic_to_shared(p);
}
__device__ __forceinline__ void cp16(unsigned s, const void* g) {
    asm volatile("cp.async.cg.shared.global [%0], [%1], 16;" :: "r"(s), "l"(g));
}
__device__ __forceinline__ void cp4(unsigned s, const void* g) {
    asm volatile("cp.async.ca.shared.global [%0], [%1], 4;" :: "r"(s), "l"(g));
}

// ---------------------------------------------------------------------------
// Scratch (__device__ globals: module-load allocated, no runtime alloc)
// ---------------------------------------------------------------------------
__device__ float g_G[(size_t)TT * BB * NRNN];      // pre-gate (FALLBACK only)
__device__ __align__(16) float g_xT[(size_t)NIN * MM];      // (FALLBACK only)
__device__ __align__(16) u64   g_WoPk[(size_t)NRNN * 18];   // (lo,hi) W_out pairs
__device__ int   g_cnt[NRNN];
__device__ int   g_idx[NRNN * NRNN];
__device__ float g_val[NRNN * NRNN];
__device__ int   g_diag = 1;   // static init; cleared only by non-diag inputs
__device__ float g_wdiag[NRNN];

// ---------------------------------------------------------------------------
// Merged prep: diag detection + W_out pack. Skipping exact zeros is
// bit-exact in fp32.
// ---------------------------------------------------------------------------
__global__ void prep_all(const float* __restrict__ W,
                         const float* __restrict__ Wout) {
    int i = blockIdx.x * blockDim.x + threadIdx.x;   // 262144 threads
    {
        int k = i >> 9;
        int n = i & (NRNN - 1);
        float w = W[(size_t)(NIN + k) * NRNN + n];
        if (k == n)          g_wdiag[n] = w;
        else if (w != 0.0f)  atomicAnd(&g_diag, 0);
    }
    if (i < NRNN * 18) {
        int k  = i / 18;
        int o2 = i - k * 18;
        float lo = (2 * o2     < NOUT) ? Wout[(size_t)k * NOUT + 2 * o2]     : 0.0f;
        float hi = (2 * o2 + 1 < NOUT) ? Wout[(size_t)k * NOUT + 2 * o2 + 1] : 0.0f;
        g_WoPk[i] = pack2(lo, hi);
    }
}

// CSC build — fallback path only.
__global__ void build_csc(const float* __restrict__ W) {
    if (g_diag) return;
    if (threadIdx.x != 0) return;
    int n = blockIdx.x;
    int c = 0;
    for (int k = 0; k < NRNN; k++) {
        float w = W[(size_t)(NIN + k) * NRNN + n];
        if (w != 0.0f) {
            g_idx[n * NRNN + c] = k;
            g_val[n * NRNN + c] = w;
            c++;
        }
    }
    g_cnt[n] = c;
}

// ===========================================================================
// FUSED diag-path kernel: gate compute + recurrence in one pass, NO g_G.
// CTA = one batch row b (128 CTAs, 512 threads; thread owns column n).
// W column in registers as 44 (w_2k, w_2k+1) pairs. Per 8-step chunk:
// x row (85 floats, cp4: 4B-aligned src) + noise rows (cp16) double-buffered.
// Per step/thread: 22 broadcast LDS.128 + 44 FFMA2 + softplus + STG.
// h chain (~44 cyc serial) hides under 352-cyc/step gate compute.
// ===========================================================================
#define XSTR 88   /* padded x row: 88 floats = 352B, 16B-aligned */
__global__ void __launch_bounds__(512, 1) fused_diag_kernel(
        const float* __restrict__ x,
        const float* __restrict__ W,
        const float* __restrict__ bias,
        const float* __restrict__ noise,
        float* __restrict__ Hout) {
    if (!g_diag) return;
    __shared__ __align__(16) float xs[2][CH][XSTR];    // 5.6 KB
    __shared__ __align__(16) float nsh[2][CH][NRNN];   // 32.8 KB

    int n   = threadIdx.x;               // 512 threads: one column each
    int b   = blockIdx.x;                // 128 CTAs

    // zero x pads once (written never again; barrier below orders vs reads)
    if (n < 2 * CH * 3) {
        int bi = n / (CH * 3);
        int r  = (n / 3) % CH;
        int p  = n % 3;
        xs[bi][r][NIN + p] = 0.0f;
    }

    // W column -> registers as 44 k-pairs (zero-padded past k=84)
    u64 wp[KP];
    #pragma unroll
    for (int kp = 0; kp < KP; kp++) {
        int k0 = 2 * kp, k1 = 2 * kp + 1;
        float wl = (k0 < NIN) ? W[(size_t)k0 * NRNN + n] : 0.0f;
        float wh = (k1 < NIN) ? W[(size_t)k1 * NRNN + n] : 0.0f;
        wp[kp] = pack2(wl, wh);
    }
    float b_n = bias[n];
    float wd  = g_wdiag[n];
    size_t e  = (size_t)b * NRNN + n;

    // stage chunk c into buffer buf: x rows via cp4 (src only 4B-aligned),
    // noise rows via cp16 (2048B row stride: 16B-aligned)
    auto stage = [&](int buf, int c) {
        int t0 = c * CH;
        for (int idx = n; idx < CH * NIN; idx += 512) {
            int i = idx / NIN;
            int k = idx - i * NIN;
            cp4(s2u(&xs[buf][i][k]),
                &x[((size_t)(t0 + i) * BB + b) * NIN + k]);
        }
        for (int idx = n; idx < CH * (NRNN / 4); idx += 512) {
            int i = idx >> 7;
            int q = idx & 127;
            cp16(s2u(&nsh[buf][i][q * 4]),
                 &noise[((size_t)(t0 + i) * BB + b) * NRNN + q * 4]);
        }
        asm volatile("cp.async.commit_group;" ::: "memory");
    };

    stage(0, 0);
    stage(1, 1);

    float h = 0.0f;
    #pragma unroll 1
    for (int c = 0; c < NCH; c++) {                  // 125 chunks x 8 steps
        if (c < NCH - 1)
            asm volatile("cp.async.wait_group 1;" ::: "memory");
        else
            asm volatile("cp.async.wait_group 0;" ::: "memory");
        __syncthreads();

        int buf = c & 1;
        #pragma unroll
        for (int i = 0; i < CH; i++) {
            const ulonglong2* xv =
                reinterpret_cast<const ulonglong2*>(&xs[buf][i][0]);
            u64 acc_a = 0ull, acc_b = 0ull;
            #pragma unroll
            for (int q = 0; q < KP / 2; q++) {       // 22 LDS.128, 44 fma2
                ulonglong2 v = xv[q];
                acc_a = fma2(v.x, wp[2 * q],     acc_a);
                acc_b = fma2(v.y, wp[2 * q + 1], acc_b);
            }
            float la, ha, lb, hb;
            unpack2(acc_a, la, ha);
            unpack2(acc_b, lb, hb);
            float gate = (la + ha) + (lb + hb) + b_n + nsh[buf][i][n];
            gate = fmaf(wd, h, gate);
            float sp = fmaxf(gate, 0.0f) + __logf(1.0f + __expf(-fabsf(gate)));
            h = 0.8f * h + 0.2f * sp;
            Hout[(size_t)(c * CH + i) * STEP + e] = h;
        }
        __syncthreads();
        if (c + 2 < NCH) stage(buf, c + 2);
    }
}

// ===========================================================================
// FALLBACK path (non-diagonal W_rec): transpose + phase1 + rec_generic.
// All predicated on !g_diag; dead launches on the diag path.
// ===========================================================================
__global__ void transpose_x(const float* __restrict__ x) {
    if (g_diag) return;
    __shared__ float tile[32][33];
    int mb  = blockIdx.x * 32;
    int kb  = blockIdx.y * 32;
    int tid = threadIdx.x;
    int tx  = tid & 31;
    int ty  = tid >> 5;
    #pragma unroll
    for (int i = ty; i < 32; i += 8) {
        int k = kb + tx;
        tile[i][tx] = (k < NIN) ? x[(size_t)(mb + i) * NIN + k] : 0.0f;
    }
    __syncthreads();
    {
        int kl = tid >> 3;
        int m4 = tid & 7;
        int k  = kb + kl;
        if (k < NIN) {
            float4 v;
            v.x = tile[m4 * 4 + 0][kl];
            v.y = tile[m4 * 4 + 1][kl];
            v.z = tile[m4 * 4 + 2][kl];
            v.w = tile[m4 * 4 + 3][kl];
            *reinterpret_cast<float4*>(&g_xT[(size_t)k * MM + mb + m4 * 4]) = v;
        }
    }
}

#define TM 128
#define TN 64
#define KT 17
#define NTILES 5
__global__ void __launch_bounds__(128, 4) phase1_kernel(
        const float* __restrict__ W,
        const float* __restrict__ bias,
        const float* __restrict__ noise) {
    if (g_diag) return;
    __shared__ __align__(16) float As[2][KT][TM];
    __shared__ __align__(16) u64   Ws[2][KT][TN / 2];

    int tid = threadIdx.x;
    int m0  = blockIdx.x * TM;
    int n0  = blockIdx.y * TN;
    int tx  = tid & 7;
    int ty  = tid >> 3;

    u64 acc[8][4] = {};

    auto stage = [&](int buf, int k0) {
        for (int idx = tid; idx < KT * 32; idx += 128) {
            int k = idx >> 5;
            int c = idx & 31;
            cp16(s2u(&As[buf][k][c * 4]),
                 &g_xT[(size_t)(k0 + k) * MM + m0 + c * 4]);
        }
        for (int idx = tid; idx < KT * 16; idx += 128) {
            int k = idx >> 4;
            int c = idx & 15;
            cp16(s2u(&Ws[buf][k][c * 2]),
                 &W[(size_t)(k0 + k) * NRNN + n0 + c * 4]);
        }
        asm volatile("cp.async.commit_group;" ::: "memory");
    };

    stage(0, 0);
    stage(1, KT);

    #pragma unroll 1
    for (int t = 0; t < NTILES; t++) {
        if (t + 1 < NTILES)
            asm volatile("cp.async.wait_group 1;" ::: "memory");
        else
            asm volatile("cp.async.wait_group 0;" ::: "memory");
        __syncthreads();

        int buf = t & 1;
        #pragma unroll
        for (int k = 0; k < KT; k++) {
            float4 a0 = *reinterpret_cast<float4*>(&As[buf][k][ty * 8]);
            float4 a1 = *reinterpret_cast<float4*>(&As[buf][k][ty * 8 + 4]);
            ulonglong2 w01 = *reinterpret_cast<ulonglong2*>(&Ws[buf][k][tx * 4]);
            ulonglong2 w23 = *reinterpret_cast<ulonglong2*>(&Ws[buf][k][tx * 4 + 2]);
            u64 ap[8] = { pack2(a0.x, a0.x), pack2(a0.y, a0.y),
                          pack2(a0.z, a0.z), pack2(a0.w, a0.w),
                          pack2(a1.x, a1.x), pack2(a1.y, a1.y),
                          pack2(a1.z, a1.z), pack2(a1.w, a1.w) };
            #pragma unroll
            for (int r = 0; r < 8; r++) {
                acc[r][0] = fma2(ap[r], w01.x, acc[r][0]);
                acc[r][1] = fma2(ap[r], w01.y, acc[r][1]);
                acc[r][2] = fma2(ap[r], w23.x, acc[r][2]);
                acc[r][3] = fma2(ap[r], w23.y, acc[r][3]);
            }
        }
        __syncthreads();
        if (t + 2 < NTILES) stage(buf, (t + 2) * KT);
    }

    float4 bb0 = *reinterpret_cast<const float4*>(&bias[n0 + tx * 8]);
    float4 bb1 = *reinterpret_cast<const float4*>(&bias[n0 + tx * 8 + 4]);

    #pragma unroll
    for (int r = 0; r < 8; r++) {
        int m = m0 + ty * 8 + r;
        size_t off = (size_t)m * NRNN + n0 + tx * 8;
        float4 nz0 = *reinterpret_cast<const float4*>(&noise[off]);
        float4 nz1 = *reinterpret_cast<const float4*>(&noise[off + 4]);
        float v0, v1, v2, v3, v4, v5, v6, v7;
        unpack2(acc[r][0], v0, v1);
        unpack2(acc[r][1], v2, v3);
        unpack2(acc[r][2], v4, v5);
        unpack2(acc[r][3], v6, v7);
        float4 o0, o1;
        o0.x = v0 + bb0.x + nz0.x;  o0.y = v1 + bb0.y + nz0.y;
        o0.z = v2 + bb0.z + nz0.z;  o0.w = v3 + bb0.w + nz0.w;
        o1.x = v4 + bb1.x + nz1.x;  o1.y = v5 + bb1.y + nz1.y;
        o1.z = v6 + bb1.z + nz1.z;  o1.w = v7 + bb1.w + nz1.w;
        *reinterpret_cast<float4*>(&g_G[off])     = o0;
        *reinterpret_cast<float4*>(&g_G[off + 4]) = o1;
    }
}

__global__ void rec_generic_kernel(float* __restrict__ Hout) {
    if (g_diag) return;
    __shared__ float hs[2][NRNN];
    int n = threadIdx.x;
    int b = blockIdx.x;

    hs[0][n] = 0.0f;

    int cnt = g_cnt[n];
    int   ki[4];
    float wv[4];
    #pragma unroll
    for (int j = 0; j < 4; j++) {
        if (j < cnt) { ki[j] = g_idx[n * NRNN + j]; wv[j] = g_val[n * NRNN + j]; }
        else         { ki[j] = 0;                    wv[j] = 0.0f; }
    }

    const float* Gb = g_G + (size_t)b * NRNN + n;
    float*       Hb = Hout + (size_t)b * NRNN + n;
    __syncthreads();

    int p = 0;
    float gcur = Gb[0];
    for (int t = 0; t < TT; t++) {
        int tn = (t + 1 < TT) ? (t + 1) : t;
        float gnext = Gb[(size_t)tn * STEP];

        float acc = gcur;
        acc = fmaf(wv[0], hs[p][ki[0]], acc);
        acc = fmaf(wv[1], hs[p][ki[1]], acc);
        acc = fmaf(wv[2], hs[p][ki[2]], acc);
        acc = fmaf(wv[3], hs[p][ki[3]], acc);
        for (int j = 4; j < cnt; j++)
            acc = fmaf(g_val[n * NRNN + j], hs[p][g_idx[n * NRNN + j]], acc);

        float sp = fmaxf(acc, 0.0f) + __logf(1.0f + __expf(-fabsf(acc)));
        float hn = 0.8f * hs[p][n] + 0.2f * sp;

        hs[p ^ 1][n] = hn;
        Hb[(size_t)t * STEP] = hn;
        __syncthreads();
        p ^= 1;
        gcur = gnext;
    }
}

// ---------------------------------------------------------------------------
// Kernel 3: y[m,o] = sigmoid(h[m,:] @ W_out[:,o] + b_out[o])
// cp.async double-buffered, P3BK=16 (R14, unchanged).
// ---------------------------------------------------------------------------
#define P3BK 16
#define P3ROWS 256
#define P3STR 20
#define NO2P 18
#define NO2  17
#define NO2G 9
__global__ void __launch_bounds__(256) phase3_kernel(
        const float* __restrict__ Hin,
        const float* __restrict__ bout,
        float* __restrict__ y) {
    __shared__ __align__(16) float hsh[2][P3ROWS][P3STR];
    __shared__ __align__(16) u64   wsh2[2][P3BK][NO2P];

    int tid = threadIdx.x;
    int g   = tid >> 7;
    int t   = tid & 127;
    int m0  = blockIdx.x * P3ROWS;
    int ob  = g * NO2G;

    u64 acc[2][NO2G] = {};

    auto stage = [&](int buf, int k0) {
        for (int idx = tid; idx < P3ROWS * 4; idx += 256) {
            int r = idx >> 2;
            int q = idx & 3;
            cp16(s2u(&hsh[buf][r][q * 4]),
                 &Hin[(size_t)(m0 + r) * NRNN + k0 + q * 4]);
        }
        for (int idx = tid; idx < P3BK * (NO2P / 2); idx += 256) {
            int k = idx / 9;
            int c = idx - k * 9;
            cp16(s2u(&wsh2[buf][k][c * 2]),
                 &g_WoPk[(size_t)(k0 + k) * NO2P + c * 2]);
        }
        asm volatile("cp.async.commit_group;" ::: "memory");
    };

    stage(0, 0);

    #pragma unroll 1
    for (int e = 0; e < NRNN / P3BK; e++) {
        if (e + 1 < NRNN / P3BK) {
            stage((e + 1) & 1, (e + 1) * P3BK);
            asm volatile("cp.async.wait_group 1;" ::: "memory");
        } else {
            asm volatile("cp.async.wait_group 0;" ::: "memory");
        }
        __syncthreads();

        int buf = e & 1;
        #pragma unroll
        for (int kk = 0; kk < P3BK; kk++) {
            float h0 = hsh[buf][t][kk];
            float h1 = hsh[buf][t + 128][kk];
            u64 hp0 = pack2(h0, h0);
            u64 hp1 = pack2(h1, h1);
            #pragma unroll
            for (int j = 0; j < NO2G; j++) {
                u64 w = wsh2[buf][kk][ob + j];
                acc[0][j] = fma2(hp0, w, acc[0][j]);
                acc[1][j] = fma2(hp1, w, acc[1][j]);
            }
        }
        __syncthreads();
    }

    #pragma unroll
    for (int j = 0; j < NO2G; j++) {
        int o2 = ob + j;
        if (o2 >= NO2) continue;
        float b0 = bout[2 * o2];
        float b1 = (2 * o2 + 1 < NOUT) ? bout[2 * o2 + 1] : 0.0f;
        #pragma unroll
        for (int i = 0; i < 2; i++) {
            int r = m0 + t + i * 128;
            float v0, v1;
            unpack2(acc[i][j], v0, v1);
            y[(size_t)r * NOUT + 2 * o2] = 1.0f / (1.0f + __expf(-(v0 + b0)));
            if (2 * o2 + 1 < NOUT)
                y[(size_t)r * NOUT + 2 * o2 + 1] = 1.0f / (1.0f + __expf(-(v1 + b1)));
        }
    }
}

// ---------------------------------------------------------------------------
// Launch. Inputs: x, W, b, W_out, b_out, noise.
// Output: [y_hat (T*B*33) | h (T*B*512)] fp32.
// ---------------------------------------------------------------------------
extern "C" void kernel_launch(void* const* d_in, const int* in_sizes, int n_in,
                              void* d_out, int out_size) {
    const float* x     = (const float*)d_in[0];
    const float* W     = (const float*)d_in[1];
    const float* b     = (const float*)d_in[2];
    const float* W_out = (const float*)d_in[3];
    const float* b_out = (const float*)d_in[4];
    const float* noise = (const float*)d_in[5];

    float* y = (float*)d_out;
    float* h = (float*)d_out + (size_t)TT * BB * NOUT;

    prep_all<<<(NRNN * NRNN) / 256, 256>>>(W, W_out);
    build_csc<<<NRNN, 32>>>(W);                              // fallback only
    fused_diag_kernel<<<BB, NRNN>>>(x, W, b, noise, h);      // FAST PATH
    transpose_x<<<dim3(MM / 32, (NIN + 31) / 32), 256>>>(x); // fallback only
    phase1_kernel<<<dim3(MM / TM, NRNN / TN), 128>>>(W, b, noise);
    rec_generic_kernel<<<BB, NRNN>>>(h);                     // fallback only
    phase3_kernel<<<MM / P3ROWS, 256>>>(h, b_out, y);
}